// round 6
// baseline (speedup 1.0000x reference)
#include <cuda_runtime.h>
#include <stdint.h>

// Problem shape (fixed by setup_inputs):
// B=1024, K=4, E=16, H=2048, I=2048
#define NE   16
#define HD   2048
#define ID   2048
#define I2D  4096
#define NP   4096      // B*K token-expert pairs

#define BM   128
#define BN   128
#define BK   16
#define PAD  132       // padded float stride (multiple of 4 for float4 alignment)

// Scratch (allocation-free rule: __device__ globals)
__device__ int   d_cnt[NE];
__device__ int   d_bucket[NE][NP];
__device__ float d_g[(size_t)NP * ID];   // 32 MB swiglu activations

union F2 { unsigned long long u; float2 f; };

__device__ __forceinline__ void fma2(unsigned long long& d,
                                     unsigned long long a,
                                     unsigned long long b) {
    // packed fp32x2 FMA: 2 FMAs per instruction on sm_103a
    asm("fma.rn.f32x2 %0, %1, %2, %0;" : "+l"(d) : "l"(a), "l"(b));
}

__device__ __forceinline__ float swiglu_pair(float xg, float xl) {
    xg = fminf(xg, 7.0f);
    xl = fminf(fmaxf(xl, -7.0f), 7.0f);
    float s = 1.0f / (1.0f + __expf(-1.702f * xg));
    return xg * s * (xl + 1.0f);
}

__global__ void zero_cnt_kernel() {
    if (threadIdx.x < NE) d_cnt[threadIdx.x] = 0;
}

__global__ void scatter_kernel(const int* __restrict__ idx) {
    int p = blockIdx.x * blockDim.x + threadIdx.x;
    if (p < NP) {
        int e = idx[p];
        int pos = atomicAdd(&d_cnt[e], 1);
        d_bucket[e][pos] = p;
    }
}

// ---------------------------------------------------------------------------
// Shared compute core: 128x128 tile, 8x8 microtile, packed f32x2 FMAs.
// A source row for local row m is ps[m] (-1 => zero row).
// ---------------------------------------------------------------------------

#define GEMM_BODY(A_ROW_PTR, KD_, B_BASE)                                      \
    __shared__ float As[BK * PAD];                                             \
    __shared__ float Bs[BK * PAD];                                             \
    __shared__ int   ps[BM];                                                   \
    int tid = threadIdx.x;                                                     \
    if (tid < BM) {                                                            \
        int r = m0 + tid;                                                      \
        ps[tid] = (r < M) ? d_bucket[e][r] : -1;                               \
    }                                                                          \
    __syncthreads();                                                           \
    const int mA0 = tid >> 2;                                                  \
    const int mA1 = mA0 + 64;                                                  \
    const int seg = (tid & 3) * 4;                                             \
    const int p0 = ps[mA0];                                                    \
    const int p1 = ps[mA1];                                                    \
    const float* aSrc0 = (p0 >= 0) ? (A_ROW_PTR(p0)) + seg : 0;                \
    const float* aSrc1 = (p1 >= 0) ? (A_ROW_PTR(p1)) + seg : 0;                \
    const float* bSrc0 = (B_BASE) + (size_t)mA0 * (KD_) + seg;                 \
    const float* bSrc1 = (B_BASE) + (size_t)mA1 * (KD_) + seg;                 \
    const int ty = tid >> 4;                                                   \
    const int tx = tid & 15;                                                   \
    F2 acc[8][4];                                                              \
    _Pragma("unroll")                                                          \
    for (int i = 0; i < 8; i++) {                                              \
        acc[i][0].u = 0ULL; acc[i][1].u = 0ULL;                                \
        acc[i][2].u = 0ULL; acc[i][3].u = 0ULL;                                \
    }                                                                          \
    float4 rA0, rA1, rB0, rB1;                                                 \
    const float4 fz = make_float4(0.f, 0.f, 0.f, 0.f);                         \
    rA0 = aSrc0 ? *(const float4*)(aSrc0) : fz;                                \
    rA1 = aSrc1 ? *(const float4*)(aSrc1) : fz;                                \
    rB0 = *(const float4*)(bSrc0);                                             \
    rB1 = *(const float4*)(bSrc1);                                             \
    for (int k0 = 0; k0 < (KD_); k0 += BK) {                                   \
        As[(seg + 0) * PAD + mA0] = rA0.x; As[(seg + 1) * PAD + mA0] = rA0.y;  \
        As[(seg + 2) * PAD + mA0] = rA0.z; As[(seg + 3) * PAD + mA0] = rA0.w;  \
        As[(seg + 0) * PAD + mA1] = rA1.x; As[(seg + 1) * PAD + mA1] = rA1.y;  \
        As[(seg + 2) * PAD + mA1] = rA1.z; As[(seg + 3) * PAD + mA1] = rA1.w;  \
        Bs[(seg + 0) * PAD + mA0] = rB0.x; Bs[(seg + 1) * PAD + mA0] = rB0.y;  \
        Bs[(seg + 2) * PAD + mA0] = rB0.z; Bs[(seg + 3) * PAD + mA0] = rB0.w;  \
        Bs[(seg + 0) * PAD + mA1] = rB1.x; Bs[(seg + 1) * PAD + mA1] = rB1.y;  \
        Bs[(seg + 2) * PAD + mA1] = rB1.z; Bs[(seg + 3) * PAD + mA1] = rB1.w;  \
        __syncthreads();                                                       \
        if (k0 + BK < (KD_)) {                                                 \
            rA0 = aSrc0 ? *(const float4*)(aSrc0 + k0 + BK) : fz;              \
            rA1 = aSrc1 ? *(const float4*)(aSrc1 + k0 + BK) : fz;              \
            rB0 = *(const float4*)(bSrc0 + k0 + BK);                           \
            rB1 = *(const float4*)(bSrc1 + k0 + BK);                           \
        }                                                                      \
        _Pragma("unroll")                                                      \
        for (int k = 0; k < BK; ++k) {                                         \
            const float* arow = &As[k * PAD + ty * 8];                         \
            const float* brow = &Bs[k * PAD + tx * 8];                         \
            float4 aA = *(const float4*)arow;                                  \
            float4 aB = *(const float4*)(arow + 4);                            \
            float4 bA = *(const float4*)brow;                                  \
            float4 bB = *(const float4*)(brow + 4);                            \
            F2 bb0, bb1, bb2, bb3;                                             \
            bb0.f = make_float2(bA.x, bA.y);                                   \
            bb1.f = make_float2(bA.z, bA.w);                                   \
            bb2.f = make_float2(bB.x, bB.y);                                   \
            bb3.f = make_float2(bB.z, bB.w);                                   \
            float aa[8] = {aA.x, aA.y, aA.z, aA.w, aB.x, aB.y, aB.z, aB.w};    \
            _Pragma("unroll")                                                  \
            for (int i = 0; i < 8; ++i) {                                      \
                F2 ai; ai.f = make_float2(aa[i], aa[i]);                       \
                fma2(acc[i][0].u, ai.u, bb0.u);                                \
                fma2(acc[i][1].u, ai.u, bb1.u);                                \
                fma2(acc[i][2].u, ai.u, bb2.u);                                \
                fma2(acc[i][3].u, ai.u, bb3.u);                                \
            }                                                                  \
        }                                                                      \
        __syncthreads();                                                       \
    }

// C[m, c] = sum_k T[token(m), k] * W1[e, c, k]  (+bias, fused swiglu -> d_g)
#define A_ROW_GATE(p) (t + (size_t)((p) >> 2) * HD)
__global__ __launch_bounds__(256, 2) void gate_up_kernel(
    const float* __restrict__ t,
    const float* __restrict__ w,      // (E, 2I, H)
    const float* __restrict__ bias)   // (E, 2I)
{
    const int e  = blockIdx.z;
    const int M  = d_cnt[e];
    const int m0 = blockIdx.y * BM;
    if (m0 >= M) return;
    const int n0 = blockIdx.x * BN;
    const float* bBase = w + ((size_t)e * I2D + n0) * HD;

    GEMM_BODY(A_ROW_GATE, HD, bBase)

    const int colBase = n0 + tx * 8;  // 8 cols = 4 (glu,lin) pairs
    float4 bbi0 = *(const float4*)(bias + (size_t)e * I2D + colBase);
    float4 bbi1 = *(const float4*)(bias + (size_t)e * I2D + colBase + 4);
#pragma unroll
    for (int i = 0; i < 8; i++) {
        int r = ty * 8 + i;
        if (m0 + r < M) {
            int p = ps[r];
            float v0 = acc[i][0].f.x + bbi0.x;
            float v1 = acc[i][0].f.y + bbi0.y;
            float v2 = acc[i][1].f.x + bbi0.z;
            float v3 = acc[i][1].f.y + bbi0.w;
            float v4 = acc[i][2].f.x + bbi1.x;
            float v5 = acc[i][2].f.y + bbi1.y;
            float v6 = acc[i][3].f.x + bbi1.z;
            float v7 = acc[i][3].f.y + bbi1.w;
            float4 g;
            g.x = swiglu_pair(v0, v1);
            g.y = swiglu_pair(v2, v3);
            g.z = swiglu_pair(v4, v5);
            g.w = swiglu_pair(v6, v7);
            *(float4*)&d_g[(size_t)p * ID + (colBase >> 1)] = g;
        }
    }
}

// out[p, c] = sum_i W2[e, c, i] * g[p, i] + bias2[e, c]
#define A_ROW_DOWN(p) (g_act + (size_t)(p) * ID)
__global__ __launch_bounds__(256, 2) void down_kernel(
    const float* __restrict__ w,      // (E, H, I)
    const float* __restrict__ bias,   // (E, H)
    float* __restrict__ out)          // (p, H)
{
    const int e  = blockIdx.z;
    const int M  = d_cnt[e];
    const int m0 = blockIdx.y * BM;
    if (m0 >= M) return;
    const int n0 = blockIdx.x * BN;
    const float* g_act = d_g;
    const float* bBase = w + ((size_t)e * HD + n0) * ID;

    GEMM_BODY(A_ROW_DOWN, ID, bBase)

    const int colBase = n0 + tx * 8;
    float4 bbi0 = *(const float4*)(bias + (size_t)e * HD + colBase);
    float4 bbi1 = *(const float4*)(bias + (size_t)e * HD + colBase + 4);
#pragma unroll
    for (int i = 0; i < 8; i++) {
        int r = ty * 8 + i;
        if (m0 + r < M) {
            int p = ps[r];
            float4 o0, o1;
            o0.x = acc[i][0].f.x + bbi0.x;
            o0.y = acc[i][0].f.y + bbi0.y;
            o0.z = acc[i][1].f.x + bbi0.z;
            o0.w = acc[i][1].f.y + bbi0.w;
            o1.x = acc[i][2].f.x + bbi1.x;
            o1.y = acc[i][2].f.y + bbi1.y;
            o1.z = acc[i][3].f.x + bbi1.z;
            o1.w = acc[i][3].f.y + bbi1.w;
            *(float4*)&out[(size_t)p * HD + colBase]     = o0;
            *(float4*)&out[(size_t)p * HD + colBase + 4] = o1;
        }
    }
}

extern "C" void kernel_launch(void* const* d_in, const int* in_sizes, int n_in,
                              void* d_out, int out_size) {
    const float* t   = (const float*)d_in[0];
    const int*   idx = (const int*)d_in[1];
    const float* w1  = (const float*)d_in[2];
    const float* b1  = (const float*)d_in[3];
    const float* w2  = (const float*)d_in[4];
    const float* b2  = (const float*)d_in[5];
    float* out = (float*)d_out;

    zero_cnt_kernel<<<1, 32>>>();
    scatter_kernel<<<NP / 256, 256>>>(idx);
    gate_up_kernel<<<dim3(I2D / BN, NP / BM, NE), 256>>>(t, w1, b1);
    down_kernel<<<dim3(HD / BN, NP / BM, NE), 256>>>(w2, b2, out);
}

// round 8
// speedup vs baseline: 2.3788x; 2.3788x over previous
#include <cuda_runtime.h>
#include <cuda_bf16.h>
#include <stdint.h>

// B=1024, K=4, E=16, H=2048, I=2048 (fp32 in/out)
#define NE   16
#define HD   2048
#define ID   2048
#define I2D  4096
#define NP   4096
#define BM   128
#define BN   128
#define KT   32            // k elements per smem stage
#define NIT  64            // 2048 / 32
#define SROW 80            // smem row stride bytes (32 bf16 = 64B data + 16B pad)
#define MATB (128 * SROW)  // 10240 B per matrix tile
#define SA_H 0
#define SA_L (1 * MATB)
#define SB_H (2 * MATB)
#define SB_L (3 * MATB)
#define STAGEB (4 * MATB)          // 40960
#define PS_OFF (2 * STAGEB)        // 81920
#define AR_OFF (PS_OFF + 512)
#define SMEM_TOTAL (AR_OFF + 512)  // 82944

__device__ int d_cnt[NE];
__device__ int d_bucket[NE][NP];
__device__ __nv_bfloat16 d_gh[(size_t)NP * ID];
__device__ __nv_bfloat16 d_gl[(size_t)NP * ID];

// ---------------- helpers ----------------
__device__ __forceinline__ uint32_t smem_u32(const void* p) {
    uint32_t a;
    asm("{ .reg .u64 t; cvta.to.shared.u64 t, %1; cvt.u32.u64 %0, t; }" : "=r"(a) : "l"(p));
    return a;
}
__device__ __forceinline__ void ldsm4(uint32_t* r, uint32_t a) {
    asm volatile("ldmatrix.sync.aligned.m8n8.x4.shared.b16 {%0,%1,%2,%3}, [%4];"
                 : "=r"(r[0]), "=r"(r[1]), "=r"(r[2]), "=r"(r[3]) : "r"(a));
}
__device__ __forceinline__ void mma16816(float* c, const uint32_t* a, uint32_t b0, uint32_t b1) {
    asm volatile("mma.sync.aligned.m16n8k16.row.col.f32.bf16.bf16.f32 "
                 "{%0,%1,%2,%3}, {%4,%5,%6,%7}, {%8,%9}, {%0,%1,%2,%3};"
                 : "+f"(c[0]), "+f"(c[1]), "+f"(c[2]), "+f"(c[3])
                 : "r"(a[0]), "r"(a[1]), "r"(a[2]), "r"(a[3]), "r"(b0), "r"(b1));
}
// fp32x4 -> bf16 hi (8B) + bf16 lo (8B)
__device__ __forceinline__ void split4(float4 v, uint2& h, uint2& l) {
    __nv_bfloat162 h01 = __floats2bfloat162_rn(v.x, v.y);
    __nv_bfloat162 h23 = __floats2bfloat162_rn(v.z, v.w);
    float2 f01 = __bfloat1622float2(h01);
    float2 f23 = __bfloat1622float2(h23);
    __nv_bfloat162 l01 = __floats2bfloat162_rn(v.x - f01.x, v.y - f01.y);
    __nv_bfloat162 l23 = __floats2bfloat162_rn(v.z - f23.x, v.w - f23.y);
    h.x = *(uint32_t*)&h01; h.y = *(uint32_t*)&h23;
    l.x = *(uint32_t*)&l01; l.y = *(uint32_t*)&l23;
}
__device__ __forceinline__ float swiglu_pair(float xg, float xl) {
    xg = fminf(xg, 7.0f);
    xl = fminf(fmaxf(xl, -7.0f), 7.0f);
    float s = 1.0f / (1.0f + __expf(-1.702f * xg));
    return xg * s * (xl + 1.0f);
}

__global__ void zero_cnt_kernel() {
    if (threadIdx.x < NE) d_cnt[threadIdx.x] = 0;
}
__global__ void scatter_kernel(const int* __restrict__ idx) {
    int p = blockIdx.x * blockDim.x + threadIdx.x;
    if (p < NP) {
        int e = idx[p];
        int pos = atomicAdd(&d_cnt[e], 1);
        d_bucket[e][pos] = p;
    }
}

// ---------------- shared compute core ----------------
// Per warp: 64(M) x 32(N), 16 m16n8k16 tiles, 3-term bf16.
__device__ __forceinline__ void compute_stage(uint32_t sbase, uint32_t aoff, uint32_t boff,
                                              float acc[16][4]) {
#pragma unroll
    for (int kc = 0; kc < 2; ++kc) {
        uint32_t Ah[4][4], Al[4][4], Bh[2][4], Bl[2][4];
#pragma unroll
        for (int mt = 0; mt < 4; ++mt) {
            ldsm4(Ah[mt], sbase + SA_H + aoff + mt * 1280 + kc * 32);
            ldsm4(Al[mt], sbase + SA_L + aoff + mt * 1280 + kc * 32);
        }
#pragma unroll
        for (int nt2 = 0; nt2 < 2; ++nt2) {
            ldsm4(Bh[nt2], sbase + SB_H + boff + nt2 * 1280 + kc * 32);
            ldsm4(Bl[nt2], sbase + SB_L + boff + nt2 * 1280 + kc * 32);
        }
#pragma unroll
        for (int mt = 0; mt < 4; ++mt)
#pragma unroll
            for (int nt = 0; nt < 4; ++nt) {
                float* c = acc[mt * 4 + nt];
                uint32_t bh0 = Bh[nt >> 1][(nt & 1) * 2], bh1 = Bh[nt >> 1][(nt & 1) * 2 + 1];
                uint32_t bl0 = Bl[nt >> 1][(nt & 1) * 2], bl1 = Bl[nt >> 1][(nt & 1) * 2 + 1];
                mma16816(c, Ah[mt], bh0, bh1);
                mma16816(c, Ah[mt], bl0, bl1);
                mma16816(c, Al[mt], bh0, bh1);
            }
    }
}

// ldmatrix per-thread offsets (within a stage's matrix tile)
__device__ __forceinline__ uint32_t a_ldsm_off(int wm, int lane) {
    return (uint32_t)(wm * 64 + (lane & 15)) * SROW + ((lane >> 4) * 16);
}
__device__ __forceinline__ uint32_t b_ldsm_off(int wn, int lane) {
    return (uint32_t)(wn * 32 + (lane & 7) + ((lane & 16) >> 1)) * SROW + ((lane & 8) * 2);
}

// ---------------- gate_up: g = swiglu(T_gather x W1^T + b1) -> d_gh/d_gl ----
__global__ __launch_bounds__(256, 1) void gate_kernel(
    const float* __restrict__ t, const float* __restrict__ w1,
    const float* __restrict__ b1) {
    const int e = blockIdx.z;
    const int M = d_cnt[e];
    const int m0 = blockIdx.x * BM;
    if (m0 >= M) return;
    const int n0 = blockIdx.y * BN;

    extern __shared__ char smem[];
    uint32_t su = smem_u32(smem);
    const int tid = threadIdx.x, lane = tid & 31, wid = tid >> 5;
    int* ps = (int*)(smem + PS_OFF);
    int* ar = (int*)(smem + AR_OFF);
    if (tid < BM) {
        int r = m0 + tid;
        int p = (r < M) ? d_bucket[e][r] : -1;
        ps[tid] = p;
        ar[tid] = (p >= 0) ? (p >> 2) : -1;
    }
    __syncthreads();

    // loader: 4 float4 chunks per matrix per thread (128 rows x 32 floats)
    uint32_t soff[4];
    const float* aP[4];
    const float* bP[4];
    bool avv[4];
    const float* wb = w1 + ((size_t)e * I2D + n0) * HD;
#pragma unroll
    for (int i = 0; i < 4; i++) {
        int c = tid + i * 256;
        int row = c >> 3, c8 = c & 7;
        soff[i] = (uint32_t)row * SROW + c8 * 8;
        int tok = ar[row];
        avv[i] = (tok >= 0);
        aP[i] = t + (size_t)(tok < 0 ? 0 : tok) * HD + c8 * 4;
        bP[i] = wb + (size_t)row * HD + c8 * 4;
    }

    const int wm = wid >> 2, wn = wid & 3;
    const uint32_t aoff = a_ldsm_off(wm, lane);
    const uint32_t boff = b_ldsm_off(wn, lane);

    float acc[16][4];
#pragma unroll
    for (int i = 0; i < 16; i++) { acc[i][0] = acc[i][1] = acc[i][2] = acc[i][3] = 0.f; }

    const float4 fz = make_float4(0.f, 0.f, 0.f, 0.f);
    float4 va[4], vb[4];
#pragma unroll
    for (int i = 0; i < 4; i++) {
        va[i] = avv[i] ? *(const float4*)(aP[i]) : fz;
        vb[i] = *(const float4*)(bP[i]);
    }
    {   // store stage 0
        char* st = smem;
#pragma unroll
        for (int i = 0; i < 4; i++) {
            uint2 h, l;
            split4(va[i], h, l);
            *(uint2*)(st + SA_H + soff[i]) = h; *(uint2*)(st + SA_L + soff[i]) = l;
            split4(vb[i], h, l);
            *(uint2*)(st + SB_H + soff[i]) = h; *(uint2*)(st + SB_L + soff[i]) = l;
        }
    }
    __syncthreads();

    for (int it = 0; it < NIT; ++it) {
        const int b = it & 1;
        if (it + 1 < NIT) {
            const int k0 = (it + 1) * KT;
#pragma unroll
            for (int i = 0; i < 4; i++) {
                va[i] = avv[i] ? *(const float4*)(aP[i] + k0) : fz;
                vb[i] = *(const float4*)(bP[i] + k0);
            }
        }
        compute_stage(su + b * STAGEB, aoff, boff, acc);
        __syncthreads();
        if (it + 1 < NIT) {
            char* st = smem + (b ^ 1) * STAGEB;
#pragma unroll
            for (int i = 0; i < 4; i++) {
                uint2 h, l;
                split4(va[i], h, l);
                *(uint2*)(st + SA_H + soff[i]) = h; *(uint2*)(st + SA_L + soff[i]) = l;
                split4(vb[i], h, l);
                *(uint2*)(st + SB_H + soff[i]) = h; *(uint2*)(st + SB_L + soff[i]) = l;
            }
            __syncthreads();
        }
    }

    // epilogue: bias + swiglu -> bf16 hi/lo activations
    const int g = lane >> 2, q = lane & 3;
    const float* bb = b1 + (size_t)e * I2D;
#pragma unroll
    for (int nt = 0; nt < 4; ++nt) {
        int n = n0 + wn * 32 + nt * 8 + q * 2;
        float bn0 = __ldg(bb + n), bn1 = __ldg(bb + n + 1);
#pragma unroll
        for (int mt = 0; mt < 4; ++mt) {
            float* c = acc[mt * 4 + nt];
            int r0 = wm * 64 + mt * 16 + g;
            if (m0 + r0 < M) {
                int p = ps[r0];
                float gg = swiglu_pair(c[0] + bn0, c[1] + bn1);
                __nv_bfloat16 h = __float2bfloat16(gg);
                __nv_bfloat16 lo = __float2bfloat16(gg - __bfloat162float(h));
                size_t o = (size_t)p * ID + (n >> 1);
                d_gh[o] = h; d_gl[o] = lo;
            }
            int r1 = r0 + 8;
            if (m0 + r1 < M) {
                int p = ps[r1];
                float gg = swiglu_pair(c[2] + bn0, c[3] + bn1);
                __nv_bfloat16 h = __float2bfloat16(gg);
                __nv_bfloat16 lo = __float2bfloat16(gg - __bfloat162float(h));
                size_t o = (size_t)p * ID + (n >> 1);
                d_gh[o] = h; d_gl[o] = lo;
            }
        }
    }
}

// ---------------- down: out = G x W2^T + b2 ----------------
__global__ __launch_bounds__(256, 1) void down_kernel(
    const float* __restrict__ w2, const float* __restrict__ b2,
    float* __restrict__ out) {
    const int e = blockIdx.z;
    const int M = d_cnt[e];
    const int m0 = blockIdx.x * BM;
    if (m0 >= M) return;
    const int n0 = blockIdx.y * BN;

    extern __shared__ char smem[];
    uint32_t su = smem_u32(smem);
    const int tid = threadIdx.x, lane = tid & 31, wid = tid >> 5;
    int* ps = (int*)(smem + PS_OFF);
    if (tid < BM) {
        int r = m0 + tid;
        ps[tid] = (r < M) ? d_bucket[e][r] : -1;
    }
    __syncthreads();

    // A loader: bf16 hi/lo, 2 x 16B chunks per thread per matrix
    uint32_t soffA[2];
    const uint4* ghP[2];
    const uint4* glP[2];
    bool avA[2];
#pragma unroll
    for (int i = 0; i < 2; i++) {
        int c = tid + i * 256;
        int row = c >> 2, c4 = c & 3;
        soffA[i] = (uint32_t)row * SROW + c4 * 16;
        int p = ps[row];
        avA[i] = (p >= 0);
        size_t off = (size_t)(p < 0 ? 0 : p) * ID + c4 * 8;
        ghP[i] = (const uint4*)(d_gh + off);
        glP[i] = (const uint4*)(d_gl + off);
    }
    // B loader: fp32 w2 with conversion
    uint32_t soffB[4];
    const float* bP[4];
    const float* wb = w2 + ((size_t)e * HD + n0) * ID;
#pragma unroll
    for (int i = 0; i < 4; i++) {
        int c = tid + i * 256;
        int row = c >> 3, c8 = c & 7;
        soffB[i] = (uint32_t)row * SROW + c8 * 8;
        bP[i] = wb + (size_t)row * ID + c8 * 4;
    }

    const int wm = wid >> 2, wn = wid & 3;
    const uint32_t aoff = a_ldsm_off(wm, lane);
    const uint32_t boff = b_ldsm_off(wn, lane);

    float acc[16][4];
#pragma unroll
    for (int i = 0; i < 16; i++) { acc[i][0] = acc[i][1] = acc[i][2] = acc[i][3] = 0.f; }

    const uint4 uz = make_uint4(0, 0, 0, 0);
    const float4 fz = make_float4(0.f, 0.f, 0.f, 0.f);
    uint4 vah[2], val[2];
    float4 vb[4];
#pragma unroll
    for (int i = 0; i < 2; i++) {
        vah[i] = avA[i] ? __ldg(ghP[i]) : uz;
        val[i] = avA[i] ? __ldg(glP[i]) : uz;
    }
#pragma unroll
    for (int i = 0; i < 4; i++) vb[i] = *(const float4*)(bP[i]);
    {
        char* st = smem;
#pragma unroll
        for (int i = 0; i < 2; i++) {
            *(uint4*)(st + SA_H + soffA[i]) = vah[i];
            *(uint4*)(st + SA_L + soffA[i]) = val[i];
        }
#pragma unroll
        for (int i = 0; i < 4; i++) {
            uint2 h, l;
            split4(vb[i], h, l);
            *(uint2*)(st + SB_H + soffB[i]) = h; *(uint2*)(st + SB_L + soffB[i]) = l;
        }
    }
    __syncthreads();

    for (int it = 0; it < NIT; ++it) {
        const int b = it & 1;
        if (it + 1 < NIT) {
            const int k0 = (it + 1) * KT;   // elements (bf16 for A, fp32 for B)
#pragma unroll
            for (int i = 0; i < 2; i++) {
                vah[i] = avA[i] ? __ldg((const uint4*)((const __nv_bfloat16*)ghP[i] + k0)) : uz;
                val[i] = avA[i] ? __ldg((const uint4*)((const __nv_bfloat16*)glP[i] + k0)) : uz;
            }
#pragma unroll
            for (int i = 0; i < 4; i++) vb[i] = *(const float4*)(bP[i] + k0);
        }
        compute_stage(su + b * STAGEB, aoff, boff, acc);
        __syncthreads();
        if (it + 1 < NIT) {
            char* st = smem + (b ^ 1) * STAGEB;
#pragma unroll
            for (int i = 0; i < 2; i++) {
                *(uint4*)(st + SA_H + soffA[i]) = vah[i];
                *(uint4*)(st + SA_L + soffA[i]) = val[i];
            }
#pragma unroll
            for (int i = 0; i < 4; i++) {
                uint2 h, l;
                split4(vb[i], h, l);
                *(uint2*)(st + SB_H + soffB[i]) = h; *(uint2*)(st + SB_L + soffB[i]) = l;
            }
            __syncthreads();
        }
    }

    // epilogue: bias, fp32 out
    const int g = lane >> 2, q = lane & 3;
    const float* bb = b2 + (size_t)e * HD;
#pragma unroll
    for (int nt = 0; nt < 4; ++nt) {
        int n = n0 + wn * 32 + nt * 8 + q * 2;
        float bn0 = __ldg(bb + n), bn1 = __ldg(bb + n + 1);
#pragma unroll
        for (int mt = 0; mt < 4; ++mt) {
            float* c = acc[mt * 4 + nt];
            int r0 = wm * 64 + mt * 16 + g;
            if (m0 + r0 < M) {
                int p = ps[r0];
                float2 v = make_float2(c[0] + bn0, c[1] + bn1);
                *(float2*)(out + (size_t)p * HD + n) = v;
            }
            int r1 = r0 + 8;
            if (m0 + r1 < M) {
                int p = ps[r1];
                float2 v = make_float2(c[2] + bn0, c[3] + bn1);
                *(float2*)(out + (size_t)p * HD + n) = v;
            }
        }
    }
}

// ---------------- launch ----------------
extern "C" void kernel_launch(void* const* d_in, const int* in_sizes, int n_in,
                              void* d_out, int out_size) {
    const float* t   = (const float*)d_in[0];
    const int*   idx = (const int*)d_in[1];
    const float* w1  = (const float*)d_in[2];
    const float* b1  = (const float*)d_in[3];
    const float* w2  = (const float*)d_in[4];
    const float* b2  = (const float*)d_in[5];
    float* out = (float*)d_out;

    static bool attr_done = false;
    if (!attr_done) {
        cudaFuncSetAttribute(gate_kernel, cudaFuncAttributeMaxDynamicSharedMemorySize, SMEM_TOTAL);
        cudaFuncSetAttribute(down_kernel, cudaFuncAttributeMaxDynamicSharedMemorySize, SMEM_TOTAL);
        attr_done = true;
    }

    zero_cnt_kernel<<<1, 32>>>();
    scatter_kernel<<<NP / 256, 256>>>(idx);
    gate_kernel<<<dim3(NP / BM, I2D / BN, NE), 256, SMEM_TOTAL>>>(t, w1, b1);
    down_kernel<<<dim3(NP / BM, HD / BN, NE), 256, SMEM_TOTAL>>>(w2, b2, out);
}